// round 1
// baseline (speedup 1.0000x reference)
#include <cuda_runtime.h>
#include <cuda_bf16.h>
#include <math.h>

// Problem dims
#define BB 4
#define LL 5
#define CIN 64
#define HH 256
#define WW 128
#define NIMG 20           // B*L
#define CHW (CIN*HH*WW)   // 2097152

// Scratch (static device globals; no allocation)
__device__ float g_neigh[NIMG * CIN * HH * WW];      // 20x64x256x128
__device__ float g_c1[NIMG * 32 * 128 * 64];
__device__ float g_c2[NIMG * 64 * 64 * 32];
__device__ float g_c3[NIMG * 64 * 32 * 16];
__device__ float g_pool[NIMG * 64];
__device__ float g_keys[NIMG * 256];
__device__ float g_attn[BB * LL];

// ---------------------------------------------------------------------------
// Kernel 1: affine grid + bilinear grid_sample (zero padding) -> g_neigh
// grid (256 h, 20 img), block 128 (w)
// ---------------------------------------------------------------------------
__global__ __launch_bounds__(128) void k_warp(const float* __restrict__ x,
                                              const float* __restrict__ nam) {
    int w = threadIdx.x;
    int h = blockIdx.x;
    int g = blockIdx.y;
    int b = g / LL, n = g % LL;
    // theta = nam[b][0][n] : (2,3)
    const float* th = nam + ((size_t)(b * LL + 0) * LL + n) * 6;
    float t00 = th[0], t01 = th[1], t02 = th[2];
    float t10 = th[3], t11 = th[4], t12 = th[5];

    float gx = (w + 0.5f) * (2.0f / WW) - 1.0f;
    float gy = (h + 0.5f) * (2.0f / HH) - 1.0f;
    float gxx = t00 * gx + t01 * gy + t02;
    float gyy = t10 * gx + t11 * gy + t12;

    float xf = ((gxx + 1.0f) * WW - 1.0f) * 0.5f;
    float yf = ((gyy + 1.0f) * HH - 1.0f) * 0.5f;
    float x0f = floorf(xf), y0f = floorf(yf);
    int x0 = (int)x0f, y0 = (int)y0f;
    int x1 = x0 + 1, y1 = y0 + 1;
    float wx1 = xf - x0f, wy1 = yf - y0f;
    float wx0 = 1.0f - wx1, wy0 = 1.0f - wy1;

    bool vx0 = (x0 >= 0) & (x0 < WW), vx1 = (x1 >= 0) & (x1 < WW);
    bool vy0 = (y0 >= 0) & (y0 < HH), vy1 = (y1 >= 0) & (y1 < HH);
    int cx0 = min(max(x0, 0), WW - 1), cx1 = min(max(x1, 0), WW - 1);
    int cy0 = min(max(y0, 0), HH - 1), cy1 = min(max(y1, 0), HH - 1);

    float w00 = wx0 * wy0 * (float)(vx0 && vy0);
    float w10 = wx1 * wy0 * (float)(vx1 && vy0);
    float w01 = wx0 * wy1 * (float)(vx0 && vy1);
    float w11 = wx1 * wy1 * (float)(vx1 && vy1);

    int a00 = cy0 * WW + cx0;
    int a10 = cy0 * WW + cx1;
    int a01 = cy1 * WW + cx0;
    int a11 = cy1 * WW + cx1;

    const float* img = x + (size_t)g * CHW;
    float* outp = g_neigh + (size_t)g * CHW + h * WW + w;
#pragma unroll 4
    for (int c = 0; c < CIN; ++c) {
        const float* ic = img + c * (HH * WW);
        float v = w00 * ic[a00] + w10 * ic[a10] + w01 * ic[a01] + w11 * ic[a11];
        outp[c * (HH * WW)] = v;
    }
}

// ---------------------------------------------------------------------------
// Kernel 2: conv1 64->32, 4x4, stride 2, pad 1, + ReLU.  in 256x128 -> 128x64
// grid (32 ohTiles, 20 img), block 256 (ow 64 x oh 4), acc[32 oc]
// ---------------------------------------------------------------------------
__global__ __launch_bounds__(256) void k_conv1(const float* __restrict__ w1,
                                               const float* __restrict__ b1) {
    __shared__ float s_in[4][10][132];
    __shared__ float4 s_w[4 * 4 * 32];   // [ci][kh][oc] -> float4 over kw

    int tid = threadIdx.x;
    int ow = tid & 63, oh_l = tid >> 6;
    int oh0 = blockIdx.x * 4;
    int g = blockIdx.y;
    const float* in = g_neigh + (size_t)g * CHW;

    float acc[32];
#pragma unroll
    for (int i = 0; i < 32; ++i) acc[i] = 0.0f;

    for (int cc = 0; cc < 64; cc += 4) {
        for (int idx = tid; idx < 4 * 4 * 32; idx += 256) {
            int oc = idx & 31, kh = (idx >> 5) & 3, ci = idx >> 7;
            const float* wp = w1 + (((size_t)oc * 64 + cc + ci) * 4 + kh) * 4;
            s_w[idx] = make_float4(wp[0], wp[1], wp[2], wp[3]);
        }
        for (int idx = tid; idx < 4 * 10 * 130; idx += 256) {
            int j = idx % 130, r = (idx / 130) % 10, ci = idx / 1300;
            int ih = 2 * oh0 - 1 + r, iw = j - 1;
            float v = 0.0f;
            if (ih >= 0 && ih < HH && iw >= 0 && iw < WW)
                v = in[(size_t)(cc + ci) * (HH * WW) + ih * WW + iw];
            s_in[ci][r][j] = v;
        }
        __syncthreads();
#pragma unroll
        for (int ci = 0; ci < 4; ++ci) {
#pragma unroll
            for (int kh = 0; kh < 4; ++kh) {
                int r = 2 * oh_l + kh;
                float iv0 = s_in[ci][r][2 * ow + 0];
                float iv1 = s_in[ci][r][2 * ow + 1];
                float iv2 = s_in[ci][r][2 * ow + 2];
                float iv3 = s_in[ci][r][2 * ow + 3];
                const float4* wrow = &s_w[(ci * 4 + kh) * 32];
#pragma unroll
                for (int oc = 0; oc < 32; ++oc) {
                    float4 wv = wrow[oc];
                    acc[oc] += iv0 * wv.x + iv1 * wv.y + iv2 * wv.z + iv3 * wv.w;
                }
            }
        }
        __syncthreads();
    }
    int oh = oh0 + oh_l;
    float* op = g_c1 + (size_t)g * 32 * 128 * 64 + oh * 64 + ow;
#pragma unroll
    for (int oc = 0; oc < 32; ++oc)
        op[(size_t)oc * 128 * 64] = fmaxf(acc[oc] + b1[oc], 0.0f);
}

// ---------------------------------------------------------------------------
// Kernel 3: conv2 32->64, 4x4, s2, p1, + ReLU.  128x64 -> 64x32
// grid (16, 20), block 128 (ow 32 x oh 4), acc[64]
// ---------------------------------------------------------------------------
__global__ __launch_bounds__(128) void k_conv2(const float* __restrict__ w2,
                                               const float* __restrict__ b2) {
    __shared__ float s_in[4][10][68];
    __shared__ float4 s_w[4 * 4 * 64];

    int tid = threadIdx.x;
    int ow = tid & 31, oh_l = tid >> 5;
    int oh0 = blockIdx.x * 4;
    int g = blockIdx.y;
    const float* in = g_c1 + (size_t)g * 32 * 128 * 64;

    float acc[64];
#pragma unroll
    for (int i = 0; i < 64; ++i) acc[i] = 0.0f;

    for (int cc = 0; cc < 32; cc += 4) {
        for (int idx = tid; idx < 4 * 4 * 64; idx += 128) {
            int oc = idx & 63, kh = (idx >> 6) & 3, ci = idx >> 8;
            const float* wp = w2 + (((size_t)oc * 32 + cc + ci) * 4 + kh) * 4;
            s_w[idx] = make_float4(wp[0], wp[1], wp[2], wp[3]);
        }
        for (int idx = tid; idx < 4 * 10 * 66; idx += 128) {
            int j = idx % 66, r = (idx / 66) % 10, ci = idx / 660;
            int ih = 2 * oh0 - 1 + r, iw = j - 1;
            float v = 0.0f;
            if (ih >= 0 && ih < 128 && iw >= 0 && iw < 64)
                v = in[(size_t)(cc + ci) * (128 * 64) + ih * 64 + iw];
            s_in[ci][r][j] = v;
        }
        __syncthreads();
#pragma unroll
        for (int ci = 0; ci < 4; ++ci) {
#pragma unroll
            for (int kh = 0; kh < 4; ++kh) {
                int r = 2 * oh_l + kh;
                float iv0 = s_in[ci][r][2 * ow + 0];
                float iv1 = s_in[ci][r][2 * ow + 1];
                float iv2 = s_in[ci][r][2 * ow + 2];
                float iv3 = s_in[ci][r][2 * ow + 3];
                const float4* wrow = &s_w[(ci * 4 + kh) * 64];
#pragma unroll
                for (int oc = 0; oc < 64; ++oc) {
                    float4 wv = wrow[oc];
                    acc[oc] += iv0 * wv.x + iv1 * wv.y + iv2 * wv.z + iv3 * wv.w;
                }
            }
        }
        __syncthreads();
    }
    int oh = oh0 + oh_l;
    float* op = g_c2 + (size_t)g * 64 * 64 * 32 + oh * 32 + ow;
#pragma unroll
    for (int oc = 0; oc < 64; ++oc)
        op[(size_t)oc * 64 * 32] = fmaxf(acc[oc] + b2[oc], 0.0f);
}

// ---------------------------------------------------------------------------
// Kernel 4: conv3 64->64, 4x4, s2, p1, + ReLU.  64x32 -> 32x16
// grid (4 ohTiles, 2 ocGroups, 20 img), block 128 (ow 16 x oh 8), acc[32]
// ---------------------------------------------------------------------------
__global__ __launch_bounds__(128) void k_conv3(const float* __restrict__ w3,
                                               const float* __restrict__ b3) {
    __shared__ float s_in[4][18][36];
    __shared__ float4 s_w[4 * 4 * 32];

    int tid = threadIdx.x;
    int ow = tid & 15, oh_l = tid >> 4;
    int oh0 = blockIdx.x * 8;
    int ocg = blockIdx.y;          // 0 or 1 -> oc base ocg*32
    int g = blockIdx.z;
    const float* in = g_c2 + (size_t)g * 64 * 64 * 32;

    float acc[32];
#pragma unroll
    for (int i = 0; i < 32; ++i) acc[i] = 0.0f;

    for (int cc = 0; cc < 64; cc += 4) {
        for (int idx = tid; idx < 4 * 4 * 32; idx += 128) {
            int oc = idx & 31, kh = (idx >> 5) & 3, ci = idx >> 7;
            const float* wp = w3 + ((((size_t)(ocg * 32 + oc)) * 64 + cc + ci) * 4 + kh) * 4;
            s_w[idx] = make_float4(wp[0], wp[1], wp[2], wp[3]);
        }
        for (int idx = tid; idx < 4 * 18 * 34; idx += 128) {
            int j = idx % 34, r = (idx / 34) % 18, ci = idx / 612;
            int ih = 2 * oh0 - 1 + r, iw = j - 1;
            float v = 0.0f;
            if (ih >= 0 && ih < 64 && iw >= 0 && iw < 32)
                v = in[(size_t)(cc + ci) * (64 * 32) + ih * 32 + iw];
            s_in[ci][r][j] = v;
        }
        __syncthreads();
#pragma unroll
        for (int ci = 0; ci < 4; ++ci) {
#pragma unroll
            for (int kh = 0; kh < 4; ++kh) {
                int r = 2 * oh_l + kh;
                float iv0 = s_in[ci][r][2 * ow + 0];
                float iv1 = s_in[ci][r][2 * ow + 1];
                float iv2 = s_in[ci][r][2 * ow + 2];
                float iv3 = s_in[ci][r][2 * ow + 3];
                const float4* wrow = &s_w[(ci * 4 + kh) * 32];
#pragma unroll
                for (int oc = 0; oc < 32; ++oc) {
                    float4 wv = wrow[oc];
                    acc[oc] += iv0 * wv.x + iv1 * wv.y + iv2 * wv.z + iv3 * wv.w;
                }
            }
        }
        __syncthreads();
    }
    int oh = oh0 + oh_l;
    float* op = g_c3 + (size_t)g * 64 * 32 * 16 + (size_t)(ocg * 32) * 512 + oh * 16 + ow;
#pragma unroll
    for (int oc = 0; oc < 32; ++oc)
        op[(size_t)oc * 512] = fmaxf(acc[oc] + b3[ocg * 32 + oc], 0.0f);
}

// ---------------------------------------------------------------------------
// Kernel 5: global average pool over 32x16 -> g_pool[20][64]
// one warp per (img, channel): 1280 warps = 160 blocks x 256
// ---------------------------------------------------------------------------
__global__ __launch_bounds__(256) void k_pool() {
    int gw = (blockIdx.x * blockDim.x + threadIdx.x) >> 5;
    int lane = threadIdx.x & 31;
    if (gw >= NIMG * 64) return;
    const float* p = g_c3 + (size_t)gw * 512;
    float s = 0.0f;
    for (int i = lane; i < 512; i += 32) s += p[i];
#pragma unroll
    for (int o = 16; o; o >>= 1) s += __shfl_xor_sync(0xFFFFFFFFu, s, o);
    if (lane == 0) g_pool[gw] = s * (1.0f / 512.0f);
}

// ---------------------------------------------------------------------------
// Kernel 6: key MLP 64->256->128->256 per image (grid 20, block 256)
// ---------------------------------------------------------------------------
__global__ __launch_bounds__(256) void k_keys(const float* __restrict__ f1w, const float* __restrict__ f1b,
                                              const float* __restrict__ f2w, const float* __restrict__ f2b,
                                              const float* __restrict__ f3w, const float* __restrict__ f3b) {
    __shared__ float p[64], h1[256], h2[128];
    int g = blockIdx.x, tid = threadIdx.x;
    if (tid < 64) p[tid] = g_pool[g * 64 + tid];
    __syncthreads();
    {
        float s = f1b[tid];
        const float* wr = f1w + (size_t)tid * 64;
#pragma unroll 8
        for (int c = 0; c < 64; ++c) s += wr[c] * p[c];
        h1[tid] = fmaxf(s, 0.0f);
    }
    __syncthreads();
    if (tid < 128) {
        float s = f2b[tid];
        const float* wr = f2w + (size_t)tid * 256;
#pragma unroll 8
        for (int c = 0; c < 256; ++c) s += wr[c] * h1[c];
        h2[tid] = fmaxf(s, 0.0f);
    }
    __syncthreads();
    {
        float s = f3b[tid];
        const float* wr = f3w + (size_t)tid * 128;
#pragma unroll 8
        for (int c = 0; c < 128; ++c) s += wr[c] * h2[c];
        g_keys[g * 256 + tid] = s;
    }
}

// ---------------------------------------------------------------------------
// Kernel 7: query MLP for image b*L, attn projection, softmax over L
// grid 4 (batch), block 256
// ---------------------------------------------------------------------------
__global__ __launch_bounds__(256) void k_attn(const float* __restrict__ f1w, const float* __restrict__ f1b,
                                              const float* __restrict__ f2w, const float* __restrict__ f2b,
                                              const float* __restrict__ f3w, const float* __restrict__ f3b,
                                              const float* __restrict__ aw, const float* __restrict__ ab) {
    __shared__ float p[64], h1[256], h2[128], qv[32], q[256], logits[8];
    int b = blockIdx.x, tid = threadIdx.x;
    int g0 = b * LL;
    if (tid < 64) p[tid] = g_pool[g0 * 64 + tid];
    __syncthreads();
    {
        float s = f1b[tid];
        const float* wr = f1w + (size_t)tid * 64;
#pragma unroll 8
        for (int c = 0; c < 64; ++c) s += wr[c] * p[c];
        h1[tid] = fmaxf(s, 0.0f);
    }
    __syncthreads();
    if (tid < 128) {
        float s = f2b[tid];
        const float* wr = f2w + (size_t)tid * 256;
#pragma unroll 8
        for (int c = 0; c < 256; ++c) s += wr[c] * h1[c];
        h2[tid] = fmaxf(s, 0.0f);
    }
    __syncthreads();
    if (tid < 32) {
        float s = f3b[tid];
        const float* wr = f3w + (size_t)tid * 128;
#pragma unroll 8
        for (int c = 0; c < 128; ++c) s += wr[c] * h2[c];
        qv[tid] = s;
    }
    __syncthreads();
    {
        float s = ab[tid];
        const float* wr = aw + (size_t)tid * 32;
#pragma unroll
        for (int j = 0; j < 32; ++j) s += wr[j] * qv[j];
        q[tid] = s;
    }
    __syncthreads();
    int wid = tid >> 5, lane = tid & 31;
    if (wid < LL) {
        const float* kr = g_keys + (size_t)(g0 + wid) * 256;
        float s = 0.0f;
        for (int i = lane; i < 256; i += 32) s += kr[i] * q[i];
#pragma unroll
        for (int o = 16; o; o >>= 1) s += __shfl_xor_sync(0xFFFFFFFFu, s, o);
        if (lane == 0) logits[wid] = s;
    }
    __syncthreads();
    if (tid == 0) {
        float m = -1e30f;
        for (int n = 0; n < LL; ++n) m = fmaxf(m, logits[n]);
        float e[LL];
        float den = 0.0f;
        for (int n = 0; n < LL; ++n) { e[n] = expf(logits[n] - m); den += e[n]; }
        float inv = 1.0f / den;
        for (int n = 0; n < LL; ++n) g_attn[b * LL + n] = e[n] * inv;
    }
}

// ---------------------------------------------------------------------------
// Kernel 8: out[b] = sum_n attn[b][n] * neigh[b*L+n]   (float4 vectorized)
// grid (2048, 4), block 256
// ---------------------------------------------------------------------------
__global__ __launch_bounds__(256) void k_fuse(float* __restrict__ out) {
    int b = blockIdx.y;
    int i = blockIdx.x * blockDim.x + threadIdx.x;   // float4 index, < CHW/4
    float a0 = g_attn[b * LL + 0];
    float a1 = g_attn[b * LL + 1];
    float a2 = g_attn[b * LL + 2];
    float a3 = g_attn[b * LL + 3];
    float a4 = g_attn[b * LL + 4];
    const float4* n0 = reinterpret_cast<const float4*>(g_neigh + (size_t)(b * LL + 0) * CHW);
    const float4* n1 = reinterpret_cast<const float4*>(g_neigh + (size_t)(b * LL + 1) * CHW);
    const float4* n2 = reinterpret_cast<const float4*>(g_neigh + (size_t)(b * LL + 2) * CHW);
    const float4* n3 = reinterpret_cast<const float4*>(g_neigh + (size_t)(b * LL + 3) * CHW);
    const float4* n4 = reinterpret_cast<const float4*>(g_neigh + (size_t)(b * LL + 4) * CHW);
    float4 v0 = n0[i], v1 = n1[i], v2 = n2[i], v3 = n3[i], v4 = n4[i];
    float4 r;
    r.x = a0 * v0.x + a1 * v1.x + a2 * v2.x + a3 * v3.x + a4 * v4.x;
    r.y = a0 * v0.y + a1 * v1.y + a2 * v2.y + a3 * v3.y + a4 * v4.y;
    r.z = a0 * v0.z + a1 * v1.z + a2 * v2.z + a3 * v3.z + a4 * v4.z;
    r.w = a0 * v0.w + a1 * v1.w + a2 * v2.w + a3 * v3.w + a4 * v4.w;
    reinterpret_cast<float4*>(out + (size_t)b * CHW)[i] = r;
}

// ---------------------------------------------------------------------------
extern "C" void kernel_launch(void* const* d_in, const int* in_sizes, int n_in,
                              void* d_out, int out_size) {
    const float* x    = (const float*)d_in[0];
    // d_in[1] = record_len (unused; reference ignores it)
    const float* nam  = (const float*)d_in[2];
    const float* w1   = (const float*)d_in[3];
    const float* b1   = (const float*)d_in[4];
    const float* w2   = (const float*)d_in[5];
    const float* b2   = (const float*)d_in[6];
    const float* w3   = (const float*)d_in[7];
    const float* b3   = (const float*)d_in[8];
    const float* kf1w = (const float*)d_in[9];
    const float* kf1b = (const float*)d_in[10];
    const float* kf2w = (const float*)d_in[11];
    const float* kf2b = (const float*)d_in[12];
    const float* kf3w = (const float*)d_in[13];
    const float* kf3b = (const float*)d_in[14];
    const float* qf1w = (const float*)d_in[15];
    const float* qf1b = (const float*)d_in[16];
    const float* qf2w = (const float*)d_in[17];
    const float* qf2b = (const float*)d_in[18];
    const float* qf3w = (const float*)d_in[19];
    const float* qf3b = (const float*)d_in[20];
    const float* aw   = (const float*)d_in[21];
    const float* ab   = (const float*)d_in[22];
    float* out = (float*)d_out;

    k_warp <<<dim3(HH, NIMG), 128>>>(x, nam);
    k_conv1<<<dim3(32, NIMG), 256>>>(w1, b1);
    k_conv2<<<dim3(16, NIMG), 128>>>(w2, b2);
    k_conv3<<<dim3(4, 2, NIMG), 128>>>(w3, b3);
    k_pool <<<160, 256>>>();
    k_keys <<<NIMG, 256>>>(kf1w, kf1b, kf2w, kf2b, kf3w, kf3b);
    k_attn <<<BB, 256>>>(qf1w, qf1b, qf2w, qf2b, qf3w, qf3b, aw, ab);
    k_fuse <<<dim3(CHW / 4 / 256, BB), 256>>>(out);
}